// round 4
// baseline (speedup 1.0000x reference)
#include <cuda_runtime.h>
#include <cuda_bf16.h>
#include <mma.h>

using namespace nvcuda;

#define BB 2048
#define NN 128
#define DD 512

typedef unsigned long long u64;

// scratch: cw planes [k][b][d], k=0 text-row, k=1 img-row. 8 MB static.
__device__ float g_cw[2 * BB * DD];

__device__ __forceinline__ float tanh_ap(float x) {
    float y;
    asm("tanh.approx.f32 %0, %1;" : "=f"(y) : "f"(x));
    return y;
}
__device__ __forceinline__ u64 ffma2(u64 a, u64 b, u64 c) {
    u64 d;
    asm("fma.rn.f32x2 %0, %1, %2, %3;" : "=l"(d) : "l"(a), "l"(b), "l"(c));
    return d;
}
__device__ __forceinline__ u64 pack2(float lo, float hi) {
    u64 r;
    asm("mov.b64 %0, {%1, %2};" : "=l"(r) : "f"(lo), "f"(hi));
    return r;
}
__device__ __forceinline__ void unpack2(u64 v, float& lo, float& hi) {
    asm("mov.b64 {%0, %1}, %2;" : "=f"(lo), "=f"(hi) : "l"(v));
}
__device__ __forceinline__ void bsplit(float x, __nv_bfloat16& h, __nv_bfloat16& l) {
    __nv_bfloat16 hh = __float2bfloat16(x);
    h = hh;
    l = __float2bfloat16(x - __bfloat162float(hh));
}

// ---------------------------------------------------------------------------
// Kernel A: cw = [text;img] @ cow via bf16 hi/lo split (3 MMAs).
// 128(M) x 128(N) tile, K-chunk 16, 256 threads, double-buffered shared.
// grid = (512/128=4, 4096/128=32) = 128 CTAs (single wave).
// ---------------------------------------------------------------------------
__global__ __launch_bounds__(256) void cw_gemm(
    const float* __restrict__ text, const float* __restrict__ img,
    const float* __restrict__ cow)
{
    const int rowBase = blockIdx.y * 128;
    const int colBase = blockIdx.x * 128;
    const int tid = threadIdx.x;
    const int warp = tid >> 5;
    const int wm = warp >> 2;      // 0..1 : rows [wm*64, wm*64+64)
    const int wn = warp & 3;       // 0..3 : cols [wn*32, wn*32+32)

    const float* __restrict__ Abase =
        (rowBase < BB) ? (text + (size_t)rowBase * DD)
                       : (img + (size_t)(rowBase - BB) * DD);

    __shared__ __nv_bfloat16 sAh[2][128][24], sAl[2][128][24];
    __shared__ __nv_bfloat16 sBh[2][16][136], sBl[2][16][136];

    float4 rA[2], rB[2];

    auto gload = [&](int kc) {
#pragma unroll
        for (int it = 0; it < 2; it++) {
            int q = tid + it * 256;
            int r = q >> 2, c4 = q & 3;
            rA[it] = *(const float4*)(Abase + (size_t)r * DD + kc + c4 * 4);
        }
#pragma unroll
        for (int it = 0; it < 2; it++) {
            int q = tid + it * 256;
            int r = q >> 5, c4 = q & 31;
            rB[it] = *(const float4*)(cow + (size_t)(kc + r) * DD + colBase + c4 * 4);
        }
    };
    auto sstore = [&](int s) {
#pragma unroll
        for (int it = 0; it < 2; it++) {
            int q = tid + it * 256;
            int r = q >> 2, c4 = q & 3;
            bsplit(rA[it].x, sAh[s][r][c4*4+0], sAl[s][r][c4*4+0]);
            bsplit(rA[it].y, sAh[s][r][c4*4+1], sAl[s][r][c4*4+1]);
            bsplit(rA[it].z, sAh[s][r][c4*4+2], sAl[s][r][c4*4+2]);
            bsplit(rA[it].w, sAh[s][r][c4*4+3], sAl[s][r][c4*4+3]);
        }
#pragma unroll
        for (int it = 0; it < 2; it++) {
            int q = tid + it * 256;
            int r = q >> 5, c4 = q & 31;
            bsplit(rB[it].x, sBh[s][r][c4*4+0], sBl[s][r][c4*4+0]);
            bsplit(rB[it].y, sBh[s][r][c4*4+1], sBl[s][r][c4*4+1]);
            bsplit(rB[it].z, sBh[s][r][c4*4+2], sBl[s][r][c4*4+2]);
            bsplit(rB[it].w, sBh[s][r][c4*4+3], sBl[s][r][c4*4+3]);
        }
    };

    wmma::fragment<wmma::accumulator, 16, 16, 16, float> acc[4][2];
#pragma unroll
    for (int i = 0; i < 4; i++)
#pragma unroll
        for (int j = 0; j < 2; j++) wmma::fill_fragment(acc[i][j], 0.0f);

    auto compute = [&](int s) {
        wmma::fragment<wmma::matrix_a, 16, 16, 16, __nv_bfloat16, wmma::row_major> ah[4], al[4];
        wmma::fragment<wmma::matrix_b, 16, 16, 16, __nv_bfloat16, wmma::row_major> bh[2], bl[2];
#pragma unroll
        for (int i = 0; i < 4; i++) {
            wmma::load_matrix_sync(ah[i], &sAh[s][wm*64 + i*16][0], 24);
            wmma::load_matrix_sync(al[i], &sAl[s][wm*64 + i*16][0], 24);
        }
#pragma unroll
        for (int j = 0; j < 2; j++) {
            wmma::load_matrix_sync(bh[j], &sBh[s][0][wn*32 + j*16], 136);
            wmma::load_matrix_sync(bl[j], &sBl[s][0][wn*32 + j*16], 136);
        }
#pragma unroll
        for (int i = 0; i < 4; i++)
#pragma unroll
            for (int j = 0; j < 2; j++) {
                wmma::mma_sync(acc[i][j], ah[i], bh[j], acc[i][j]);
                wmma::mma_sync(acc[i][j], ah[i], bl[j], acc[i][j]);
                wmma::mma_sync(acc[i][j], al[i], bh[j], acc[i][j]);
            }
    };

    gload(0);
    sstore(0);
    __syncthreads();
    int cur = 0;
    for (int kc = 16; kc < DD; kc += 16) {
        gload(kc);
        compute(cur);
        sstore(cur ^ 1);
        __syncthreads();
        cur ^= 1;
    }
    compute(cur);

    float* C = g_cw + (size_t)rowBase * DD;
#pragma unroll
    for (int i = 0; i < 4; i++)
#pragma unroll
        for (int j = 0; j < 2; j++)
            wmma::store_matrix_sync(
                C + (size_t)(wm*64 + i*16) * DD + colBase + wn*32 + j*16,
                acc[i][j], DD, wmma::mem_row_major);
}

// ---------------------------------------------------------------------------
// Kernel B: fused co-attention. One CTA per sample, 4 warps, 1 row per warp.
// No online softmax (|logit| <= sum|W_co| ~ 18, exp is safe in fp32).
// c0/c1/W_co read from shared in-loop to keep regs <= 128 (4 CTAs/SM).
// ---------------------------------------------------------------------------
__global__ __launch_bounds__(128, 4) void fused_coattn(
    const float* __restrict__ text, const float* __restrict__ img,
    const float* __restrict__ comment, const int* __restrict__ comment_num,
    const float* __restrict__ W_ca, const float* __restrict__ W_co,
    float* __restrict__ out)
{
    const int b = blockIdx.x;
    const int tid = threadIdx.x;
    const int lane = tid & 31;
    const int warp = tid >> 5;
    const int M = comment_num[b];
    const float* __restrict__ comment_b = comment + (size_t)b * NN * DD;

    __shared__ float s_c0[DD], s_c1[DD], s_Wca[DD], s_Wco[DD];
    __shared__ float s_red[4][3 * DD];
    __shared__ float s_z[4];
    __shared__ float s_scalar[8];

    for (int i = tid; i < DD / 4; i += 128) {
        ((float4*)s_c0)[i]  = ((const float4*)(text + (size_t)b * DD))[i];
        ((float4*)s_c1)[i]  = ((const float4*)(img  + (size_t)b * DD))[i];
        ((float4*)s_Wca)[i] = ((const float4*)W_ca)[i];
        ((float4*)s_Wco)[i] = ((const float4*)W_co)[i];
    }
    __syncthreads();

    // packed cw vectors (d = 4*(j*32+lane)+c; u64 i=2j -> c=0,1; 2j+1 -> c=2,3)
    u64 cw0p[8], cw1p[8];
    {
        const float* cw0g = g_cw + (size_t)b * DD;
        const float* cw1g = g_cw + (size_t)BB * DD + (size_t)b * DD;
#pragma unroll
        for (int j = 0; j < 4; j++) {
            ulonglong2 t0 = *(const ulonglong2*)(cw0g + 4 * (j * 32 + lane));
            ulonglong2 t1 = *(const ulonglong2*)(cw1g + 4 * (j * 32 + lane));
            cw0p[2*j] = t0.x; cw0p[2*j+1] = t0.y;
            cw1p[2*j] = t1.x; cw1p[2*j+1] = t1.y;
        }
    }

    u64 acc0p[8], acc1p[8], aap[8];
#pragma unroll
    for (int i = 0; i < 8; i++) { acc0p[i] = 0ull; acc1p[i] = 0ull; aap[i] = 0ull; }
    float Zrun = 0.f;

    u64 znext[8];
    if (warp < M) {
        const float4* p = (const float4*)(comment_b + (size_t)warp * DD);
#pragma unroll
        for (int j = 0; j < 4; j++) {
            float4 t = __ldcs(p + j * 32 + lane);
            znext[2*j] = pack2(t.x, t.y);
            znext[2*j+1] = pack2(t.z, t.w);
        }
    }

    for (int n = warp; n < M; n += 4) {
        u64 z[8];
#pragma unroll
        for (int i = 0; i < 8; i++) z[i] = znext[i];
        if (n + 4 < M) {
            const float4* p = (const float4*)(comment_b + (size_t)(n + 4) * DD);
#pragma unroll
            for (int j = 0; j < 4; j++) {
                float4 t = __ldcs(p + j * 32 + lane);
                znext[2*j] = pack2(t.x, t.y);
                znext[2*j+1] = pack2(t.z, t.w);
            }
        }

        // dots s0 = cw0.z, s1 = cw1.z
        u64 p0 = 0ull, p1 = 0ull;
#pragma unroll
        for (int i = 0; i < 8; i++) {
            p0 = ffma2(cw0p[i], z[i], p0);
            p1 = ffma2(cw1p[i], z[i], p1);
        }
        float x, y, s0, s1;
        unpack2(p0, x, y); s0 = x + y;
        unpack2(p1, x, y); s1 = x + y;
#pragma unroll
        for (int o = 16; o; o >>= 1) {
            s0 += __shfl_xor_sync(0xffffffffu, s0, o);
            s1 += __shfl_xor_sync(0xffffffffu, s1, o);
        }
        float w0 = tanh_ap(s0), w1 = tanh_ap(s1);
        const u64 w0p = pack2(w0, w0);
        const u64 w1p = pack2(w1, w1);

        // accumulate co_w*z; comment-attention logit
        float l = 0.f;
#pragma unroll
        for (int j = 0; j < 4; j++) {
            const int off = 4 * (j * 32 + lane);
            ulonglong2 c0v = *(const ulonglong2*)(s_c0 + off);
            ulonglong2 c1v = *(const ulonglong2*)(s_c1 + off);
            float4 wv = *(const float4*)(s_Wco + off);
#pragma unroll
            for (int h = 0; h < 2; h++) {
                const int i = 2 * j + h;
                const u64 c0 = h ? c0v.y : c0v.x;
                const u64 c1 = h ? c1v.y : c1v.x;
                acc0p[i] = ffma2(w0p, z[i], acc0p[i]);
                acc1p[i] = ffma2(w1p, z[i], acc1p[i]);
                u64 v = ffma2(w0p, c0, ffma2(w1p, c1, z[i]));
                unpack2(v, x, y);
                l = fmaf(tanh_ap(x), h ? wv.z : wv.x, l);
                l = fmaf(tanh_ap(y), h ? wv.w : wv.y, l);
            }
        }
#pragma unroll
        for (int o = 16; o; o >>= 1) l += __shfl_xor_sync(0xffffffffu, l, o);

        // plain softmax accumulation (logits bounded, no max needed)
        float p = __expf(l);
        Zrun += p;
        const u64 pp = pack2(p, p);
#pragma unroll
        for (int i = 0; i < 8; i++) aap[i] = ffma2(pp, z[i], aap[i]);
    }

    // spill per-warp partials
#pragma unroll
    for (int j = 0; j < 4; j++) {
        const int off = 4 * (j * 32 + lane);
        *(ulonglong2*)(s_red[warp] + off)        = make_ulonglong2(acc0p[2*j], acc0p[2*j+1]);
        *(ulonglong2*)(s_red[warp] + DD + off)   = make_ulonglong2(acc1p[2*j], acc1p[2*j+1]);
        *(ulonglong2*)(s_red[warp] + 2*DD + off) = make_ulonglong2(aap[2*j],   aap[2*j+1]);
    }
    if (lane == 0) s_z[warp] = Zrun;
    __syncthreads();

    // cross-warp combine; thread t owns d = 4t..4t+3
    float Zg = s_z[0] + s_z[1] + s_z[2] + s_z[3];
    float invZ = 1.f / Zg;

    float a0[4] = {0,0,0,0}, a1[4] = {0,0,0,0}, av[4] = {0,0,0,0};
#pragma unroll
    for (int w = 0; w < 4; w++) {
        float4 x0 = *(const float4*)(s_red[w] + 4*tid);
        float4 x1 = *(const float4*)(s_red[w] + DD + 4*tid);
        float4 xa = *(const float4*)(s_red[w] + 2*DD + 4*tid);
        a0[0]+=x0.x; a0[1]+=x0.y; a0[2]+=x0.z; a0[3]+=x0.w;
        a1[0]+=x1.x; a1[1]+=x1.y; a1[2]+=x1.z; a1[3]+=x1.w;
        av[0]+=xa.x; av[1]+=xa.y; av[2]+=xa.z; av[3]+=xa.w;
    }

    float4 c0v = *(const float4*)(s_c0 + 4*tid);
    float4 c1v = *(const float4*)(s_c1 + 4*tid);
    float4 wca = *(const float4*)(s_Wca + 4*tid);
    float cl0 = tanh_ap(c0v.x + a0[0]) * wca.x + tanh_ap(c0v.y + a0[1]) * wca.y
              + tanh_ap(c0v.z + a0[2]) * wca.z + tanh_ap(c0v.w + a0[3]) * wca.w;
    float cl1 = tanh_ap(c1v.x + a1[0]) * wca.x + tanh_ap(c1v.y + a1[1]) * wca.y
              + tanh_ap(c1v.z + a1[2]) * wca.z + tanh_ap(c1v.w + a1[3]) * wca.w;
#pragma unroll
    for (int o = 16; o; o >>= 1) {
        cl0 += __shfl_xor_sync(0xffffffffu, cl0, o);
        cl1 += __shfl_xor_sync(0xffffffffu, cl1, o);
    }
    if (lane == 0) { s_scalar[warp] = cl0; s_scalar[4 + warp] = cl1; }
    __syncthreads();
    cl0 = s_scalar[0] + s_scalar[1] + s_scalar[2] + s_scalar[3];
    cl1 = s_scalar[4] + s_scalar[5] + s_scalar[6] + s_scalar[7];

    float mx = fmaxf(cl0, cl1);
    float e0 = __expf(cl0 - mx), e1 = __expf(cl1 - mx);
    float einv = 1.f / (e0 + e1);
    float wc0 = e0 * einv, wc1 = e1 * einv;

    float4 o1;
    o1.x = fmaf(c0v.x, wc0, c1v.x * wc1);
    o1.y = fmaf(c0v.y, wc0, c1v.y * wc1);
    o1.z = fmaf(c0v.z, wc0, c1v.z * wc1);
    o1.w = fmaf(c0v.w, wc0, c1v.w * wc1);
    *(float4*)(out + (size_t)b * DD + 4*tid) = o1;

    float4 o2 = make_float4(av[0]*invZ, av[1]*invZ, av[2]*invZ, av[3]*invZ);
    *(float4*)(out + (size_t)BB * DD + (size_t)b * DD + 4*tid) = o2;

    if (tid == 0) {
        out[(size_t)2 * BB * DD + (size_t)b * 2 + 0] = wc0;
        out[(size_t)2 * BB * DD + (size_t)b * 2 + 1] = wc1;
    }
}

extern "C" void kernel_launch(void* const* d_in, const int* in_sizes, int n_in,
                              void* d_out, int out_size)
{
    (void)in_sizes; (void)n_in; (void)out_size;
    const float* text        = (const float*)d_in[0];
    const float* img         = (const float*)d_in[1];
    const float* comment     = (const float*)d_in[2];
    const int*   comment_num = (const int*)d_in[3];
    const float* cow         = (const float*)d_in[4];
    const float* W_ca        = (const float*)d_in[5];
    const float* W_co        = (const float*)d_in[7];
    float* out = (float*)d_out;

    dim3 gg(DD / 128, 4096 / 128);
    cw_gemm<<<gg, 256>>>(text, img, cow);
    fused_coattn<<<BB, 128>>>(text, img, comment, comment_num, W_ca, W_co, out);
}

// round 5
// speedup vs baseline: 1.3551x; 1.3551x over previous
#include <cuda_runtime.h>
#include <cuda_bf16.h>
#include <mma.h>

using namespace nvcuda;

#define BB 2048
#define NN 128
#define DD 512

typedef unsigned long long u64;

// static scratch (no allocs allowed)
__device__ float g_cw[2 * BB * DD];                    // 8 MB
__device__ __nv_bfloat16 g_Ah[2 * BB * DD];            // 4 MB  [text;img] hi
__device__ __nv_bfloat16 g_Al[2 * BB * DD];            // 4 MB  lo
__device__ __nv_bfloat16 g_Bh[DD * DD];                // 512 KB cow hi
__device__ __nv_bfloat16 g_Bl[DD * DD];                // 512 KB cow lo

__device__ __forceinline__ float tanh_ap(float x) {
    float y;
    asm("tanh.approx.f32 %0, %1;" : "=f"(y) : "f"(x));
    return y;
}
__device__ __forceinline__ u64 ffma2(u64 a, u64 b, u64 c) {
    u64 d;
    asm("fma.rn.f32x2 %0, %1, %2, %3;" : "=l"(d) : "l"(a), "l"(b), "l"(c));
    return d;
}
__device__ __forceinline__ u64 pack2(float lo, float hi) {
    u64 r;
    asm("mov.b64 %0, {%1, %2};" : "=l"(r) : "f"(lo), "f"(hi));
    return r;
}
__device__ __forceinline__ void unpack2(u64 v, float& lo, float& hi) {
    asm("mov.b64 {%0, %1}, %2;" : "=f"(lo), "=f"(hi) : "l"(v));
}
__device__ __forceinline__ void bsplit(float x, __nv_bfloat16& h, __nv_bfloat16& l) {
    __nv_bfloat16 hh = __float2bfloat16(x);
    h = hh;
    l = __float2bfloat16(x - __bfloat162float(hh));
}
__device__ __forceinline__ void cpa_wait(int pend) {
    switch (pend) {
        case 0: asm volatile("cp.async.wait_group 0;" ::: "memory"); break;
        case 1: asm volatile("cp.async.wait_group 1;" ::: "memory"); break;
        case 2: asm volatile("cp.async.wait_group 2;" ::: "memory"); break;
        default: asm volatile("cp.async.wait_group 3;" ::: "memory"); break;
    }
}

// ---------------------------------------------------------------------------
// Kernel 0: one-shot fp32 -> bf16 hi/lo split of A=[text;img] and B=cow.
// grid = 2048 (A) + 256 (B) blocks of 256 threads, 4 elems/thread.
// ---------------------------------------------------------------------------
__global__ __launch_bounds__(256) void convert_inputs(
    const float* __restrict__ text, const float* __restrict__ img,
    const float* __restrict__ cow)
{
    const int bid = blockIdx.x;
    __nv_bfloat16 h[4], l[4];
    if (bid < 2048) {
        const int e = (bid * 256 + threadIdx.x) * 4;
        const int r = e >> 9, c = e & 511;
        const float* src = (r < BB) ? (text + (size_t)r * DD + c)
                                    : (img + (size_t)(r - BB) * DD + c);
        float4 v = *(const float4*)src;
        bsplit(v.x, h[0], l[0]); bsplit(v.y, h[1], l[1]);
        bsplit(v.z, h[2], l[2]); bsplit(v.w, h[3], l[3]);
        uint2 uh, ul;
        uh.x = (unsigned)__bfloat16_as_ushort(h[0]) | ((unsigned)__bfloat16_as_ushort(h[1]) << 16);
        uh.y = (unsigned)__bfloat16_as_ushort(h[2]) | ((unsigned)__bfloat16_as_ushort(h[3]) << 16);
        ul.x = (unsigned)__bfloat16_as_ushort(l[0]) | ((unsigned)__bfloat16_as_ushort(l[1]) << 16);
        ul.y = (unsigned)__bfloat16_as_ushort(l[2]) | ((unsigned)__bfloat16_as_ushort(l[3]) << 16);
        *(uint2*)&g_Ah[e] = uh;
        *(uint2*)&g_Al[e] = ul;
    } else {
        const int e = ((bid - 2048) * 256 + threadIdx.x) * 4;
        float4 v = *(const float4*)(cow + e);
        bsplit(v.x, h[0], l[0]); bsplit(v.y, h[1], l[1]);
        bsplit(v.z, h[2], l[2]); bsplit(v.w, h[3], l[3]);
        uint2 uh, ul;
        uh.x = (unsigned)__bfloat16_as_ushort(h[0]) | ((unsigned)__bfloat16_as_ushort(h[1]) << 16);
        uh.y = (unsigned)__bfloat16_as_ushort(h[2]) | ((unsigned)__bfloat16_as_ushort(h[3]) << 16);
        ul.x = (unsigned)__bfloat16_as_ushort(l[0]) | ((unsigned)__bfloat16_as_ushort(l[1]) << 16);
        ul.y = (unsigned)__bfloat16_as_ushort(l[2]) | ((unsigned)__bfloat16_as_ushort(l[3]) << 16);
        *(uint2*)&g_Bh[e] = uh;
        *(uint2*)&g_Bl[e] = ul;
    }
}

// ---------------------------------------------------------------------------
// Kernel A: cw = A @ cow from preconverted bf16 hi/lo (3 MMA split).
// 128x128 tile, K-chunk 32, 256 threads, reg-staged single shared buffer.
// grid = (4, 32) = 128 CTAs (single wave).
// ---------------------------------------------------------------------------
__global__ __launch_bounds__(256) void cw_gemm()
{
    const int rowBase = blockIdx.y * 128;
    const int colBase = blockIdx.x * 128;
    const int tid = threadIdx.x;
    const int warp = tid >> 5;
    const int wm = warp >> 2;      // 0..1 : rows [wm*64, wm*64+64)
    const int wn = warp & 3;       // 0..3 : cols [wn*32, wn*32+32)

    __shared__ __nv_bfloat16 sAh[128][40], sAl[128][40];   // 32 used, pad->80B rows
    __shared__ __nv_bfloat16 sBh[32][136], sBl[32][136];

    uint4 rAh[2], rAl[2], rBh[2], rBl[2];

    auto gload = [&](int kc) {
#pragma unroll
        for (int it = 0; it < 2; it++) {
            int q = tid + it * 256;
            int r = q >> 2, c8 = (q & 3) * 8;
            rAh[it] = *(const uint4*)&g_Ah[(size_t)(rowBase + r) * DD + kc + c8];
            rAl[it] = *(const uint4*)&g_Al[(size_t)(rowBase + r) * DD + kc + c8];
        }
#pragma unroll
        for (int it = 0; it < 2; it++) {
            int q = tid + it * 256;
            int r = q >> 4, c8 = (q & 15) * 8;
            rBh[it] = *(const uint4*)&g_Bh[(size_t)(kc + r) * DD + colBase + c8];
            rBl[it] = *(const uint4*)&g_Bl[(size_t)(kc + r) * DD + colBase + c8];
        }
    };
    auto sstore = [&]() {
#pragma unroll
        for (int it = 0; it < 2; it++) {
            int q = tid + it * 256;
            int r = q >> 2, c8 = (q & 3) * 8;
            *(uint4*)&sAh[r][c8] = rAh[it];
            *(uint4*)&sAl[r][c8] = rAl[it];
        }
#pragma unroll
        for (int it = 0; it < 2; it++) {
            int q = tid + it * 256;
            int r = q >> 4, c8 = (q & 15) * 8;
            *(uint4*)&sBh[r][c8] = rBh[it];
            *(uint4*)&sBl[r][c8] = rBl[it];
        }
    };

    wmma::fragment<wmma::accumulator, 16, 16, 16, float> acc[4][2];
#pragma unroll
    for (int i = 0; i < 4; i++)
#pragma unroll
        for (int j = 0; j < 2; j++) wmma::fill_fragment(acc[i][j], 0.0f);

    auto compute = [&]() {
#pragma unroll
        for (int ks = 0; ks < 32; ks += 16) {
            wmma::fragment<wmma::matrix_a, 16, 16, 16, __nv_bfloat16, wmma::row_major> ah[4], al[4];
            wmma::fragment<wmma::matrix_b, 16, 16, 16, __nv_bfloat16, wmma::row_major> bh[2], bl[2];
#pragma unroll
            for (int i = 0; i < 4; i++) {
                wmma::load_matrix_sync(ah[i], &sAh[wm*64 + i*16][ks], 40);
                wmma::load_matrix_sync(al[i], &sAl[wm*64 + i*16][ks], 40);
            }
#pragma unroll
            for (int j = 0; j < 2; j++) {
                wmma::load_matrix_sync(bh[j], &sBh[ks][wn*32 + j*16], 136);
                wmma::load_matrix_sync(bl[j], &sBl[ks][wn*32 + j*16], 136);
            }
#pragma unroll
            for (int i = 0; i < 4; i++)
#pragma unroll
                for (int j = 0; j < 2; j++) {
                    wmma::mma_sync(acc[i][j], ah[i], bh[j], acc[i][j]);
                    wmma::mma_sync(acc[i][j], ah[i], bl[j], acc[i][j]);
                    wmma::mma_sync(acc[i][j], al[i], bh[j], acc[i][j]);
                }
        }
    };

    gload(0);
    sstore();
    __syncthreads();
    for (int kc = 32; kc < DD; kc += 32) {
        gload(kc);
        compute();
        __syncthreads();
        sstore();
        __syncthreads();
    }
    compute();

    float* C = g_cw + (size_t)rowBase * DD;
#pragma unroll
    for (int i = 0; i < 4; i++)
#pragma unroll
        for (int j = 0; j < 2; j++)
            wmma::store_matrix_sync(
                C + (size_t)(wm*64 + i*16) * DD + colBase + wn*32 + j*16,
                acc[i][j], DD, wmma::mem_row_major);
}

// ---------------------------------------------------------------------------
// Kernel B: fused co-attention. One CTA per sample, 4 warps, 1 row per warp
// iteration, cp.async 4-stage per-warp ring for 4 rows of DRAM MLP.
// cw/c0/c1 in registers; Wco from shared. Ring aliased as reduction scratch.
// ---------------------------------------------------------------------------
__global__ __launch_bounds__(128, 3) void fused_coattn(
    const float* __restrict__ text, const float* __restrict__ img,
    const float* __restrict__ comment, const int* __restrict__ comment_num,
    const float* __restrict__ W_ca, const float* __restrict__ W_co,
    float* __restrict__ out)
{
    const int b = blockIdx.x;
    const int tid = threadIdx.x;
    const int lane = tid & 31;
    const int warp = tid >> 5;
    const int M = comment_num[b];
    const float* __restrict__ comment_b = comment + (size_t)b * NN * DD;

    __shared__ float s_ring[4][4][512];     // 32 KB: [warp][stage][row floats]; aliased later
    __shared__ float s_c0[DD], s_c1[DD], s_Wca[DD], s_Wco[DD];
    __shared__ float s_z[4];
    __shared__ float s_scalar[8];

    for (int i = tid; i < DD / 4; i += 128) {
        ((float4*)s_c0)[i]  = ((const float4*)(text + (size_t)b * DD))[i];
        ((float4*)s_c1)[i]  = ((const float4*)(img  + (size_t)b * DD))[i];
        ((float4*)s_Wca)[i] = ((const float4*)W_ca)[i];
        ((float4*)s_Wco)[i] = ((const float4*)W_co)[i];
    }
    __syncthreads();

    // packed register vectors (d = 4*(j*32+lane)+c; u64 i=2j -> c=0,1; 2j+1 -> c=2,3)
    u64 cw0p[8], cw1p[8], c0p[8], c1p[8];
    {
        const float* cw0g = g_cw + (size_t)b * DD;
        const float* cw1g = g_cw + (size_t)BB * DD + (size_t)b * DD;
#pragma unroll
        for (int j = 0; j < 4; j++) {
            const int off = 4 * (j * 32 + lane);
            ulonglong2 t0 = *(const ulonglong2*)(cw0g + off);
            ulonglong2 t1 = *(const ulonglong2*)(cw1g + off);
            ulonglong2 u0 = *(const ulonglong2*)(s_c0 + off);
            ulonglong2 u1 = *(const ulonglong2*)(s_c1 + off);
            cw0p[2*j] = t0.x; cw0p[2*j+1] = t0.y;
            cw1p[2*j] = t1.x; cw1p[2*j+1] = t1.y;
            c0p[2*j]  = u0.x; c0p[2*j+1]  = u0.y;
            c1p[2*j]  = u1.x; c1p[2*j+1]  = u1.y;
        }
    }

    u64 acc0p[8], acc1p[8], aap[8];
#pragma unroll
    for (int i = 0; i < 8; i++) { acc0p[i] = 0ull; acc1p[i] = 0ull; aap[i] = 0ull; }
    float Zrun = 0.f;

    const int cnt = (M > warp) ? ((M - warp + 3) >> 2) : 0;   // rows for this warp
    const unsigned ring_addr =
        (unsigned)__cvta_generic_to_shared(&s_ring[warp][0][0]);

    auto issue_row = [&](int t) {
        const float* g = comment_b + (size_t)(warp + 4 * t) * DD + lane * 4;
        const unsigned s = ring_addr + ((unsigned)(t & 3) << 11) + ((unsigned)lane << 4);
#pragma unroll
        for (int j = 0; j < 4; j++)
            asm volatile("cp.async.cg.shared.global [%0], [%1], 16;"
                         :: "r"(s + j * 512), "l"(g + j * 128) : "memory");
        asm volatile("cp.async.commit_group;" ::: "memory");
    };

    const int pro = cnt < 4 ? cnt : 4;
    for (int t = 0; t < pro; t++) issue_row(t);

    for (int t = 0; t < cnt; t++) {
        int pend = cnt - 1 - t;
        cpa_wait(pend > 3 ? 3 : pend);

        u64 z[8];
        const float* zs = &s_ring[warp][t & 3][0];
#pragma unroll
        for (int j = 0; j < 4; j++) {
            ulonglong2 q = *(const ulonglong2*)(zs + j * 128 + lane * 4);
            z[2*j] = q.x; z[2*j+1] = q.y;
        }
        if (t + 4 < cnt) issue_row(t + 4);

        // dots s0 = cw0.z, s1 = cw1.z
        u64 p0 = 0ull, p1 = 0ull;
#pragma unroll
        for (int i = 0; i < 8; i++) {
            p0 = ffma2(cw0p[i], z[i], p0);
            p1 = ffma2(cw1p[i], z[i], p1);
        }
        float x, y, s0, s1;
        unpack2(p0, x, y); s0 = x + y;
        unpack2(p1, x, y); s1 = x + y;
#pragma unroll
        for (int o = 16; o; o >>= 1) {
            s0 += __shfl_xor_sync(0xffffffffu, s0, o);
            s1 += __shfl_xor_sync(0xffffffffu, s1, o);
        }
        const float w0 = tanh_ap(s0), w1 = tanh_ap(s1);
        const u64 w0p = pack2(w0, w0);
        const u64 w1p = pack2(w1, w1);

        // accumulate co_w*z; comment-attention logit
        float l = 0.f;
#pragma unroll
        for (int j = 0; j < 4; j++) {
            float4 wv = *(const float4*)(s_Wco + 4 * (j * 32 + lane));
#pragma unroll
            for (int h = 0; h < 2; h++) {
                const int i = 2 * j + h;
                acc0p[i] = ffma2(w0p, z[i], acc0p[i]);
                acc1p[i] = ffma2(w1p, z[i], acc1p[i]);
                u64 v = ffma2(w0p, c0p[i], ffma2(w1p, c1p[i], z[i]));
                unpack2(v, x, y);
                l = fmaf(tanh_ap(x), h ? wv.z : wv.x, l);
                l = fmaf(tanh_ap(y), h ? wv.w : wv.y, l);
            }
        }
#pragma unroll
        for (int o = 16; o; o >>= 1) l += __shfl_xor_sync(0xffffffffu, l, o);

        // plain softmax accumulation (|l| <= ||W_co||_1 ~ 18, exp safe)
        const float p = __expf(l);
        Zrun += p;
        const u64 pp = pack2(p, p);
#pragma unroll
        for (int i = 0; i < 8; i++) aap[i] = ffma2(pp, z[i], aap[i]);
    }

    // spill per-warp partials into this warp's own ring region (done with it)
    float* rw = &s_ring[warp][0][0];   // 2048 floats, private to this warp
#pragma unroll
    for (int j = 0; j < 4; j++) {
        const int off = 4 * (j * 32 + lane);
        *(ulonglong2*)(rw + off)        = make_ulonglong2(acc0p[2*j], acc0p[2*j+1]);
        *(ulonglong2*)(rw + 512 + off)  = make_ulonglong2(acc1p[2*j], acc1p[2*j+1]);
        *(ulonglong2*)(rw + 1024 + off) = make_ulonglong2(aap[2*j],   aap[2*j+1]);
    }
    if (lane == 0) s_z[warp] = Zrun;
    __syncthreads();

    // cross-warp combine; thread t owns d = 4t..4t+3
    const float Zg = s_z[0] + s_z[1] + s_z[2] + s_z[3];
    const float invZ = 1.f / Zg;

    float a0[4] = {0,0,0,0}, a1[4] = {0,0,0,0}, av[4] = {0,0,0,0};
#pragma unroll
    for (int w = 0; w < 4; w++) {
        const float* rb = &s_ring[w][0][0];
        float4 x0 = *(const float4*)(rb + 4*tid);
        float4 x1 = *(const float4*)(rb + 512 + 4*tid);
        float4 xa = *(const float4*)(rb + 1024 + 4*tid);
        a0[0]+=x0.x; a0[1]+=x0.y; a0[2]+=x0.z; a0[3]+=x0.w;
        a1[0]+=x1.x; a1[1]+=x1.y; a1[2]+=x1.z; a1[3]+=x1.w;
        av[0]+=xa.x; av[1]+=xa.y; av[2]+=xa.z; av[3]+=xa.w;
    }

    float4 c0v = *(const float4*)(s_c0 + 4*tid);
    float4 c1v = *(const float4*)(s_c1 + 4*tid);
    float4 wca = *(const float4*)(s_Wca + 4*tid);
    float cl0 = tanh_ap(c0v.x + a0[0]) * wca.x + tanh_ap(c0v.y + a0[1]) * wca.y
              + tanh_ap(c0v.z + a0[2]) * wca.z + tanh_ap(c0v.w + a0[3]) * wca.w;
    float cl1 = tanh_ap(c1v.x + a1[0]) * wca.x + tanh_ap(c1v.y + a1[1]) * wca.y
              + tanh_ap(c1v.z + a1[2]) * wca.z + tanh_ap(c1v.w + a1[3]) * wca.w;
#pragma unroll
    for (int o = 16; o; o >>= 1) {
        cl0 += __shfl_xor_sync(0xffffffffu, cl0, o);
        cl1 += __shfl_xor_sync(0xffffffffu, cl1, o);
    }
    if (lane == 0) { s_scalar[warp] = cl0; s_scalar[4 + warp] = cl1; }
    __syncthreads();
    cl0 = s_scalar[0] + s_scalar[1] + s_scalar[2] + s_scalar[3];
    cl1 = s_scalar[4] + s_scalar[5] + s_scalar[6] + s_scalar[7];

    const float mx = fmaxf(cl0, cl1);
    const float e0 = __expf(cl0 - mx), e1 = __expf(cl1 - mx);
    const float einv = 1.f / (e0 + e1);
    const float wc0 = e0 * einv, wc1 = e1 * einv;

    float4 o1;
    o1.x = fmaf(c0v.x, wc0, c1v.x * wc1);
    o1.y = fmaf(c0v.y, wc0, c1v.y * wc1);
    o1.z = fmaf(c0v.z, wc0, c1v.z * wc1);
    o1.w = fmaf(c0v.w, wc0, c1v.w * wc1);
    *(float4*)(out + (size_t)b * DD + 4*tid) = o1;

    float4 o2 = make_float4(av[0]*invZ, av[1]*invZ, av[2]*invZ, av[3]*invZ);
    *(float4*)(out + (size_t)BB * DD + (size_t)b * DD + 4*tid) = o2;

    if (tid == 0) {
        out[(size_t)2 * BB * DD + (size_t)b * 2 + 0] = wc0;
        out[(size_t)2 * BB * DD + (size_t)b * 2 + 1] = wc1;
    }
}

extern "C" void kernel_launch(void* const* d_in, const int* in_sizes, int n_in,
                              void* d_out, int out_size)
{
    (void)in_sizes; (void)n_in; (void)out_size;
    const float* text        = (const float*)d_in[0];
    const float* img         = (const float*)d_in[1];
    const float* comment     = (const float*)d_in[2];
    const int*   comment_num = (const int*)d_in[3];
    const float* cow         = (const float*)d_in[4];
    const float* W_ca        = (const float*)d_in[5];
    const float* W_co        = (const float*)d_in[7];
    float* out = (float*)d_out;

    convert_inputs<<<2048 + 256, 256>>>(text, img, cow);
    dim3 gg(DD / 128, 4096 / 128);
    cw_gemm<<<gg, 256>>>();
    fused_coattn<<<BB, 128>>>(text, img, comment, comment_num, W_ca, W_co, out);
}

// round 12
// speedup vs baseline: 1.4665x; 1.0822x over previous
#include <cuda_runtime.h>
#include <cuda_bf16.h>
#include <mma.h>

using namespace nvcuda;

#define BB 2048
#define NN 128
#define DD 512

typedef unsigned long long u64;

// static scratch (no allocs allowed)
__device__ float g_cw[2 * BB * DD];                    // 8 MB
__device__ __nv_bfloat16 g_Ah[2 * BB * DD];            // 4 MB  [text;img] hi
__device__ __nv_bfloat16 g_Al[2 * BB * DD];            // 4 MB  lo
__device__ __nv_bfloat16 g_Bh[DD * DD];                // 512 KB cow hi
__device__ __nv_bfloat16 g_Bl[DD * DD];                // 512 KB cow lo

__device__ __forceinline__ float tanh_ap(float x) {
    float y;
    asm("tanh.approx.f32 %0, %1;" : "=f"(y) : "f"(x));
    return y;
}
__device__ __forceinline__ u64 ffma2(u64 a, u64 b, u64 c) {
    u64 d;
    asm("fma.rn.f32x2 %0, %1, %2, %3;" : "=l"(d) : "l"(a), "l"(b), "l"(c));
    return d;
}
__device__ __forceinline__ u64 pack2(float lo, float hi) {
    u64 r;
    asm("mov.b64 %0, {%1, %2};" : "=l"(r) : "f"(lo), "f"(hi));
    return r;
}
__device__ __forceinline__ void unpack2(u64 v, float& lo, float& hi) {
    asm("mov.b64 {%0, %1}, %2;" : "=f"(lo), "=f"(hi) : "l"(v));
}
__device__ __forceinline__ void bsplit(float x, __nv_bfloat16& h, __nv_bfloat16& l) {
    __nv_bfloat16 hh = __float2bfloat16(x);
    h = hh;
    l = __float2bfloat16(x - __bfloat162float(hh));
}
__device__ __forceinline__ void cpa_wait(int pend) {
    if (pend <= 0) asm volatile("cp.async.wait_group 0;" ::: "memory");
    else           asm volatile("cp.async.wait_group 1;" ::: "memory");
}

// ---------------------------------------------------------------------------
// Kernel 0: one-shot fp32 -> bf16 hi/lo split of A=[text;img] and B=cow.
// ---------------------------------------------------------------------------
__global__ __launch_bounds__(256) void convert_inputs(
    const float* __restrict__ text, const float* __restrict__ img,
    const float* __restrict__ cow)
{
    const int bid = blockIdx.x;
    __nv_bfloat16 h[4], l[4];
    if (bid < 2048) {
        const int e = (bid * 256 + threadIdx.x) * 4;
        const int r = e >> 9, c = e & 511;
        const float* src = (r < BB) ? (text + (size_t)r * DD + c)
                                    : (img + (size_t)(r - BB) * DD + c);
        float4 v = *(const float4*)src;
        bsplit(v.x, h[0], l[0]); bsplit(v.y, h[1], l[1]);
        bsplit(v.z, h[2], l[2]); bsplit(v.w, h[3], l[3]);
        uint2 uh, ul;
        uh.x = (unsigned)__bfloat16_as_ushort(h[0]) | ((unsigned)__bfloat16_as_ushort(h[1]) << 16);
        uh.y = (unsigned)__bfloat16_as_ushort(h[2]) | ((unsigned)__bfloat16_as_ushort(h[3]) << 16);
        ul.x = (unsigned)__bfloat16_as_ushort(l[0]) | ((unsigned)__bfloat16_as_ushort(l[1]) << 16);
        ul.y = (unsigned)__bfloat16_as_ushort(l[2]) | ((unsigned)__bfloat16_as_ushort(l[3]) << 16);
        *(uint2*)&g_Ah[e] = uh;
        *(uint2*)&g_Al[e] = ul;
    } else {
        const int e = ((bid - 2048) * 256 + threadIdx.x) * 4;
        float4 v = *(const float4*)(cow + e);
        bsplit(v.x, h[0], l[0]); bsplit(v.y, h[1], l[1]);
        bsplit(v.z, h[2], l[2]); bsplit(v.w, h[3], l[3]);
        uint2 uh, ul;
        uh.x = (unsigned)__bfloat16_as_ushort(h[0]) | ((unsigned)__bfloat16_as_ushort(h[1]) << 16);
        uh.y = (unsigned)__bfloat16_as_ushort(h[2]) | ((unsigned)__bfloat16_as_ushort(h[3]) << 16);
        ul.x = (unsigned)__bfloat16_as_ushort(l[0]) | ((unsigned)__bfloat16_as_ushort(l[1]) << 16);
        ul.y = (unsigned)__bfloat16_as_ushort(l[2]) | ((unsigned)__bfloat16_as_ushort(l[3]) << 16);
        *(uint2*)&g_Bh[e] = uh;
        *(uint2*)&g_Bl[e] = ul;
    }
}

// ---------------------------------------------------------------------------
// Kernel A: cw = A @ cow from preconverted bf16 hi/lo (3 MMA split).
// 128x128 tile, K-chunk 32, 256 threads. grid = (4, 32).
// ---------------------------------------------------------------------------
__global__ __launch_bounds__(256) void cw_gemm()
{
    const int rowBase = blockIdx.y * 128;
    const int colBase = blockIdx.x * 128;
    const int tid = threadIdx.x;
    const int warp = tid >> 5;
    const int wm = warp >> 2;
    const int wn = warp & 3;

    __shared__ __nv_bfloat16 sAh[128][40], sAl[128][40];
    __shared__ __nv_bfloat16 sBh[32][136], sBl[32][136];

    uint4 rAh[2], rAl[2], rBh[2], rBl[2];

    auto gload = [&](int kc) {
#pragma unroll
        for (int it = 0; it < 2; it++) {
            int q = tid + it * 256;
            int r = q >> 2, c8 = (q & 3) * 8;
            rAh[it] = *(const uint4*)&g_Ah[(size_t)(rowBase + r) * DD + kc + c8];
            rAl[it] = *(const uint4*)&g_Al[(size_t)(rowBase + r) * DD + kc + c8];
        }
#pragma unroll
        for (int it = 0; it < 2; it++) {
            int q = tid + it * 256;
            int r = q >> 4, c8 = (q & 15) * 8;
            rBh[it] = *(const uint4*)&g_Bh[(size_t)(kc + r) * DD + colBase + c8];
            rBl[it] = *(const uint4*)&g_Bl[(size_t)(kc + r) * DD + colBase + c8];
        }
    };
    auto sstore = [&]() {
#pragma unroll
        for (int it = 0; it < 2; it++) {
            int q = tid + it * 256;
            int r = q >> 2, c8 = (q & 3) * 8;
            *(uint4*)&sAh[r][c8] = rAh[it];
            *(uint4*)&sAl[r][c8] = rAl[it];
        }
#pragma unroll
        for (int it = 0; it < 2; it++) {
            int q = tid + it * 256;
            int r = q >> 4, c8 = (q & 15) * 8;
            *(uint4*)&sBh[r][c8] = rBh[it];
            *(uint4*)&sBl[r][c8] = rBl[it];
        }
    };

    wmma::fragment<wmma::accumulator, 16, 16, 16, float> acc[4][2];
#pragma unroll
    for (int i = 0; i < 4; i++)
#pragma unroll
        for (int j = 0; j < 2; j++) wmma::fill_fragment(acc[i][j], 0.0f);

    auto compute = [&]() {
#pragma unroll
        for (int ks = 0; ks < 32; ks += 16) {
            wmma::fragment<wmma::matrix_a, 16, 16, 16, __nv_bfloat16, wmma::row_major> ah[4], al[4];
            wmma::fragment<wmma::matrix_b, 16, 16, 16, __nv_bfloat16, wmma::row_major> bh[2], bl[2];
#pragma unroll
            for (int i = 0; i < 4; i++) {
                wmma::load_matrix_sync(ah[i], &sAh[wm*64 + i*16][ks], 40);
                wmma::load_matrix_sync(al[i], &sAl[wm*64 + i*16][ks], 40);
            }
#pragma unroll
            for (int j = 0; j < 2; j++) {
                wmma::load_matrix_sync(bh[j], &sBh[ks][wn*32 + j*16], 136);
                wmma::load_matrix_sync(bl[j], &sBl[ks][wn*32 + j*16], 136);
            }
#pragma unroll
            for (int i = 0; i < 4; i++)
#pragma unroll
                for (int j = 0; j < 2; j++) {
                    wmma::mma_sync(acc[i][j], ah[i], bh[j], acc[i][j]);
                    wmma::mma_sync(acc[i][j], ah[i], bl[j], acc[i][j]);
                    wmma::mma_sync(acc[i][j], al[i], bh[j], acc[i][j]);
                }
        }
    };

    gload(0);
    sstore();
    __syncthreads();
    for (int kc = 32; kc < DD; kc += 32) {
        gload(kc);
        compute();
        __syncthreads();
        sstore();
        __syncthreads();
    }
    compute();

    float* C = g_cw + (size_t)rowBase * DD;
#pragma unroll
    for (int i = 0; i < 4; i++)
#pragma unroll
        for (int j = 0; j < 2; j++)
            wmma::store_matrix_sync(
                C + (size_t)(wm*64 + i*16) * DD + colBase + wn*32 + j*16,
                acc[i][j], DD, wmma::mem_row_major);
}

// ---------------------------------------------------------------------------
// Kernel B: fused co-attention. One CTA/sample, 4 warps. Row-PAIR per
// iteration from a 2-stage x 2-row cp.async ring (4 rows in flight/warp).
// Warp w handles rows {8t+2w, 8t+2w+1}. Invalid row b is ZEROED in registers
// before any use (matches reference's zeroed padded rows).
// ---------------------------------------------------------------------------
__global__ __launch_bounds__(128, 3) void fused_coattn(
    const float* __restrict__ text, const float* __restrict__ img,
    const float* __restrict__ comment, const int* __restrict__ comment_num,
    const float* __restrict__ W_ca, const float* __restrict__ W_co,
    float* __restrict__ out)
{
    const int b = blockIdx.x;
    const int tid = threadIdx.x;
    const int lane = tid & 31;
    const int warp = tid >> 5;
    const int M = comment_num[b];
    const float* __restrict__ comment_b = comment + (size_t)b * NN * DD;

    __shared__ float s_ring[4][2][2][512];  // 32 KB [warp][stage][row][float]; aliased later
    __shared__ float s_c0[DD], s_c1[DD], s_Wca[DD], s_Wco[DD];
    __shared__ float s_z[4];
    __shared__ float s_scalar[8];

    for (int i = tid; i < DD / 4; i += 128) {
        ((float4*)s_c0)[i]  = ((const float4*)(text + (size_t)b * DD))[i];
        ((float4*)s_c1)[i]  = ((const float4*)(img  + (size_t)b * DD))[i];
        ((float4*)s_Wca)[i] = ((const float4*)W_ca)[i];
        ((float4*)s_Wco)[i] = ((const float4*)W_co)[i];
    }
    __syncthreads();

    // packed cw register vectors (d = 4*(j*32+lane)+c)
    u64 cw0p[8], cw1p[8];
    {
        const float* cw0g = g_cw + (size_t)b * DD;
        const float* cw1g = g_cw + (size_t)BB * DD + (size_t)b * DD;
#pragma unroll
        for (int j = 0; j < 4; j++) {
            const int off = 4 * (j * 32 + lane);
            ulonglong2 t0 = *(const ulonglong2*)(cw0g + off);
            ulonglong2 t1 = *(const ulonglong2*)(cw1g + off);
            cw0p[2*j] = t0.x; cw0p[2*j+1] = t0.y;
            cw1p[2*j] = t1.x; cw1p[2*j+1] = t1.y;
        }
    }

    u64 acc0p[8], acc1p[8], aap[8];
#pragma unroll
    for (int i = 0; i < 8; i++) { acc0p[i] = 0ull; acc1p[i] = 0ull; aap[i] = 0ull; }
    float Zrun = 0.f;

    // pairs for this warp: rows r0 = 2*warp + 8t, r1 = r0+1
    const int cnt = (M > 2 * warp) ? ((M - 2 * warp + 7) >> 3) : 0;
    const unsigned ring_addr =
        (unsigned)__cvta_generic_to_shared(&s_ring[warp][0][0][0]);

    auto issue_pair = [&](int t) {
        const int r0 = 2 * warp + 8 * t;
        const int r1 = (r0 + 1 < NN) ? r0 + 1 : r0;   // clamp; invalid row zeroed in regs
        const float* g0 = comment_b + (size_t)r0 * DD + lane * 4;
        const float* g1 = comment_b + (size_t)r1 * DD + lane * 4;
        const unsigned s = ring_addr + ((unsigned)(t & 1) << 12) + ((unsigned)lane << 4);
#pragma unroll
        for (int j = 0; j < 4; j++)
            asm volatile("cp.async.cg.shared.global [%0], [%1], 16;"
                         :: "r"(s + j * 512), "l"(g0 + j * 128) : "memory");
#pragma unroll
        for (int j = 0; j < 4; j++)
            asm volatile("cp.async.cg.shared.global [%0], [%1], 16;"
                         :: "r"(s + 2048 + j * 512), "l"(g1 + j * 128) : "memory");
        asm volatile("cp.async.commit_group;" ::: "memory");
    };

    if (cnt > 0) issue_pair(0);
    if (cnt > 1) issue_pair(1);

    for (int t = 0; t < cnt; t++) {
        const int pend = cnt - 1 - t;
        cpa_wait(pend);

        const bool vb = (2 * warp + 8 * t + 1) < M;

        u64 za[8], zb[8];
        const float* zs = &s_ring[warp][t & 1][0][0];
#pragma unroll
        for (int j = 0; j < 4; j++) {
            ulonglong2 qa = *(const ulonglong2*)(zs + j * 128 + lane * 4);
            ulonglong2 qb = *(const ulonglong2*)(zs + 512 + j * 128 + lane * 4);
            za[2*j] = qa.x; za[2*j+1] = qa.y;
            zb[2*j] = qb.x; zb[2*j+1] = qb.y;
        }
        // CORRECTNESS GATE: zero invalid row b before ANY use (reference zeroes
        // padded rows before all einsums). tanh(0)=0, acc += w*0 = 0, exp gated.
        if (!vb) {
#pragma unroll
            for (int i = 0; i < 8; i++) zb[i] = 0ull;
        }
        if (t + 2 < cnt) issue_pair(t + 2);

        // dots: 4 independent chains
        u64 p0a = 0ull, p1a = 0ull, p0b = 0ull, p1b = 0ull;
#pragma unroll
        for (int i = 0; i < 8; i++) {
            p0a = ffma2(cw0p[i], za[i], p0a);
            p1a = ffma2(cw1p[i], za[i], p1a);
            p0b = ffma2(cw0p[i], zb[i], p0b);
            p1b = ffma2(cw1p[i], zb[i], p1b);
        }
        float x, y, s0a, s1a, s0b, s1b;
        unpack2(p0a, x, y); s0a = x + y;
        unpack2(p1a, x, y); s1a = x + y;
        unpack2(p0b, x, y); s0b = x + y;
        unpack2(p1b, x, y); s1b = x + y;
#pragma unroll
        for (int o = 16; o; o >>= 1) {
            s0a += __shfl_xor_sync(0xffffffffu, s0a, o);
            s1a += __shfl_xor_sync(0xffffffffu, s1a, o);
            s0b += __shfl_xor_sync(0xffffffffu, s0b, o);
            s1b += __shfl_xor_sync(0xffffffffu, s1b, o);
        }
        const float w0a = tanh_ap(s0a), w1a = tanh_ap(s1a);
        const float w0b = tanh_ap(s0b), w1b = tanh_ap(s1b);
        const u64 w0ap = pack2(w0a, w0a), w1ap = pack2(w1a, w1a);
        const u64 w0bp = pack2(w0b, w0b), w1bp = pack2(w1b, w1b);

        // accumulate co_w*z; comment logits for both rows
        u64 lpa = 0ull, lpb = 0ull;
#pragma unroll
        for (int j = 0; j < 4; j++) {
            const int off = 4 * (j * 32 + lane);
            ulonglong2 c0v = *(const ulonglong2*)(s_c0 + off);
            ulonglong2 c1v = *(const ulonglong2*)(s_c1 + off);
            ulonglong2 wv  = *(const ulonglong2*)(s_Wco + off);
#pragma unroll
            for (int h = 0; h < 2; h++) {
                const int i = 2 * j + h;
                const u64 c0 = h ? c0v.y : c0v.x;
                const u64 c1 = h ? c1v.y : c1v.x;
                const u64 wc = h ? wv.y  : wv.x;
                acc0p[i] = ffma2(w0ap, za[i], acc0p[i]);
                acc1p[i] = ffma2(w1ap, za[i], acc1p[i]);
                u64 va = ffma2(w0ap, c0, ffma2(w1ap, c1, za[i]));
                unpack2(va, x, y);
                lpa = ffma2(pack2(tanh_ap(x), tanh_ap(y)), wc, lpa);

                acc0p[i] = ffma2(w0bp, zb[i], acc0p[i]);
                acc1p[i] = ffma2(w1bp, zb[i], acc1p[i]);
                u64 vb2 = ffma2(w0bp, c0, ffma2(w1bp, c1, zb[i]));
                unpack2(vb2, x, y);
                lpb = ffma2(pack2(tanh_ap(x), tanh_ap(y)), wc, lpb);
            }
        }
        float la, lb;
        unpack2(lpa, x, y); la = x + y;
        unpack2(lpb, x, y); lb = x + y;
#pragma unroll
        for (int o = 16; o; o >>= 1) {
            la += __shfl_xor_sync(0xffffffffu, la, o);
            lb += __shfl_xor_sync(0xffffffffu, lb, o);
        }

        // plain softmax accumulation (|l| <= ||W_co||_1 ~ 18)
        const float pa = __expf(la);
        Zrun += pa;
        const u64 ppa = pack2(pa, pa);
#pragma unroll
        for (int i = 0; i < 8; i++) aap[i] = ffma2(ppa, za[i], aap[i]);
        if (vb) {
            const float pb = __expf(lb);
            Zrun += pb;
            const u64 ppb = pack2(pb, pb);
#pragma unroll
            for (int i = 0; i < 8; i++) aap[i] = ffma2(ppb, zb[i], aap[i]);
        }
    }

    // spill per-warp partials into own ring region
    float* rw = &s_ring[warp][0][0][0];
#pragma unroll
    for (int j = 0; j < 4; j++) {
        const int off = 4 * (j * 32 + lane);
        *(ulonglong2*)(rw + off)        = make_ulonglong2(acc0p[2*j], acc0p[2*j+1]);
        *(ulonglong2*)(rw + 512 + off)  = make_ulonglong2(acc1p[2*j], acc1p[2*j+1]);
        *(ulonglong2*)(rw + 1024 + off) = make_ulonglong2(aap[2*j],   aap[2*j+1]);
    }
    if (lane == 0) s_z[warp] = Zrun;
    __syncthreads();

    const float Zg = s_z[0] + s_z[1] + s_z[2] + s_z[3];
    const float invZ = 1.f / Zg;

    float a0[4] = {0,0,0,0}, a1[4] = {0,0,0,0}, av[4] = {0,0,0,0};
#pragma unroll
    for (int w = 0; w < 4; w++) {
        const float* rb = &s_ring[w][0][0][0];
        float4 x0 = *(const float4*)(rb + 4*tid);
        float4 x1 = *(const float4*)(rb + 512 + 4*tid);
        float4 xa = *(const float4*)(rb + 1024 + 4*tid);
        a0[0]+=x0.x; a0[1]+=x0.y; a0[2]+=x0.z; a0[3]+=x0.w;
        a1[0]+=x1.x; a1[1]+=x1.y; a1[2]+=x1.z; a1[3]+=x1.w;
        av[0]+=xa.x; av[1]+=xa.y; av[2]+=xa.z; av[3]+=xa.w;
    }

    float4 c0v = *(const float4*)(s_c0 + 4*tid);
    float4 c1v = *(const float4*)(s_c1 + 4*tid);
    float4 wca = *(const float4*)(s_Wca + 4*tid);
    float cl0 = tanh_ap(c0v.x + a0[0]) * wca.x + tanh_ap(c0v.y + a0[1]) * wca.y
              + tanh_ap(c0v.z + a0[2]) * wca.z + tanh_ap(c0v.w + a0[3]) * wca.w;
    float cl1 = tanh_ap(c1v.x + a1[0]) * wca.x + tanh_ap(c1v.y + a1[1]) * wca.y
              + tanh_ap(c1v.z + a1[2]) * wca.z + tanh_ap(c1v.w + a1[3]) * wca.w;
#pragma unroll
    for (int o = 16; o; o >>= 1) {
        cl0 += __shfl_xor_sync(0xffffffffu, cl0, o);
        cl1 += __shfl_xor_sync(0xffffffffu, cl1, o);
    }
    if (lane == 0) { s_scalar[warp] = cl0; s_scalar[4 + warp] = cl1; }
    __syncthreads();
    cl0 = s_scalar[0] + s_scalar[1] + s_scalar[2] + s_scalar[3];
    cl1 = s_scalar[4] + s_scalar[5] + s_scalar[6] + s_scalar[7];

    const float mx = fmaxf(cl0, cl1);
    const float e0 = __expf(cl0 - mx), e1 = __expf(cl1 - mx);
    const float einv = 1.f / (e0 + e1);
    const float wc0 = e0 * einv, wc1 = e1 * einv;

    float4 o1;
    o1.x = fmaf(c0v.x, wc0, c1v.x * wc1);
    o1.y = fmaf(c0v.y, wc0, c1v.y * wc1);
    o1.z = fmaf(c0v.z, wc0, c1v.z * wc1);
    o1.w = fmaf(c0v.w, wc0, c1v.w * wc1);
    *(float4*)(out + (size_t)b * DD + 4*tid) = o1;

    float4 o2 = make_float4(av[0]*invZ, av[1]*invZ, av[2]*invZ, av[3]*invZ);
    *(float4*)(out + (size_t)BB * DD + (size_t)b * DD + 4*tid) = o2;

    if (tid == 0) {
        out[(size_t)2 * BB * DD + (size_t)b * 2 + 0] = wc0;
        out[(size_t)2 * BB * DD + (size_t)b * 2 + 1] = wc1;
    }
}

extern "C" void kernel_launch(void* const* d_in, const int* in_sizes, int n_in,
                              void* d_out, int out_size)
{
    (void)in_sizes; (void)n_in; (void)out_size;
    const float* text        = (const float*)d_in[0];
    const float* img         = (const float*)d_in[1];
    const float* comment     = (const float*)d_in[2];
    const int*   comment_num = (const int*)d_in[3];
    const float* cow         = (const float*)d_in[4];
    const float* W_ca        = (const float*)d_in[5];
    const float* W_co        = (const float*)d_in[7];
    float* out = (float*)d_out;

    convert_inputs<<<2048 + 256, 256>>>(text, img, cow);
    dim3 gg(DD / 128, 4096 / 128);
    cw_gemm<<<gg, 256>>>();
    fused_coattn<<<BB, 128>>>(text, img, comment, comment_num, W_ca, W_co, out);
}